// round 6
// baseline (speedup 1.0000x reference)
#include <cuda_runtime.h>
#include <cuda_bf16.h>
#include <cstdint>

#define NN 50000
#define NE 600000
#define DD 128
#define NL 5

// ---------------- scratch ----------------
__device__ int   g_is64;
__device__ int   g_deg[NN];
__device__ int   g_cursor[NN];
__device__ int   g_rowptr[NN + 1];
__device__ int   g_col[NE];
__device__ float g_h0[NN * DD];
__device__ float g_h1[NN * DD];

// split-bf16 weights, transposed: w1 as [L][256 n][128 k], w2 as [L][128 n][256 k]
__device__ __nv_bfloat16 g_w1h[NL * 256 * 128];
__device__ __nv_bfloat16 g_w1l[NL * 256 * 128];
__device__ __nv_bfloat16 g_w2h[NL * 128 * 256];
__device__ __nv_bfloat16 g_w2l[NL * 128 * 256];

#define STILE 1024
#define NTILE ((NN + STILE - 1) / STILE)
__device__ int g_tsum[NTILE];

// ---------------- helpers ----------------
__device__ __forceinline__ float leaky(float v) { return v > 0.f ? v : 0.2f * v; }

__device__ __forceinline__ void split2(float a, float b, uint32_t& hw, uint32_t& lw) {
    __nv_bfloat16 ha = __float2bfloat16(a);
    __nv_bfloat16 hb = __float2bfloat16(b);
    float ra = a - __bfloat162float(ha);
    float rb = b - __bfloat162float(hb);
    __nv_bfloat16 la = __float2bfloat16(ra);
    __nv_bfloat16 lb = __float2bfloat16(rb);
    hw = (uint32_t)__bfloat16_as_ushort(ha) | ((uint32_t)__bfloat16_as_ushort(hb) << 16);
    lw = (uint32_t)__bfloat16_as_ushort(la) | ((uint32_t)__bfloat16_as_ushort(lb) << 16);
}

__device__ __forceinline__ void mma16816(float* d, const uint32_t* a, const uint32_t* b) {
    asm volatile(
        "mma.sync.aligned.m16n8k16.row.col.f32.bf16.bf16.f32 "
        "{%0,%1,%2,%3}, {%4,%5,%6,%7}, {%8,%9}, {%0,%1,%2,%3};"
        : "+f"(d[0]), "+f"(d[1]), "+f"(d[2]), "+f"(d[3])
        : "r"(a[0]), "r"(a[1]), "r"(a[2]), "r"(a[3]), "r"(b[0]), "r"(b[1]));
}

// ---------------- dtype detect ----------------
__global__ void detect_kernel(const int* __restrict__ p) {
    if (threadIdx.x == 0) {
        int acc = 0;
#pragma unroll
        for (int i = 0; i < 64; i++) acc |= p[2 * i + 1];
        g_is64 = (acc == 0) ? 1 : 0;
    }
}
__device__ __forceinline__ int edge_at(const int* __restrict__ p, int idx) {
    return g_is64 ? p[2 * idx] : p[idx];
}

// ---------------- CSR build ----------------
__global__ void zero_kernel() {
    int i = blockIdx.x * blockDim.x + threadIdx.x;
    if (i < NN) { g_deg[i] = 0; g_cursor[i] = 0; }
}
__global__ void hist_kernel(const int* __restrict__ ei) {
    int e = blockIdx.x * blockDim.x + threadIdx.x;
    if (e < NE) atomicAdd(&g_deg[edge_at(ei, NE + e)], 1);
}
__global__ void reduce_kernel() {
    int b = blockIdx.x, t = threadIdx.x;
    int s = 0;
#pragma unroll
    for (int j = 0; j < 4; j++) {
        int i = b * STILE + t * 4 + j;
        if (i < NN) s += g_deg[i];
    }
#pragma unroll
    for (int o = 16; o; o >>= 1) s += __shfl_down_sync(~0u, s, o);
    __shared__ int ws[8];
    if ((t & 31) == 0) ws[t >> 5] = s;
    __syncthreads();
    if (t == 0) {
        int tot = 0;
#pragma unroll
        for (int w = 0; w < 8; w++) tot += ws[w];
        g_tsum[b] = tot;
    }
}
__global__ void scantop_kernel() {
    if (threadIdx.x == 0) {
        int a = 0;
        for (int i = 0; i < NTILE; i++) { int v = g_tsum[i]; g_tsum[i] = a; a += v; }
    }
}
__global__ void scantile_kernel() {
    int b = blockIdx.x, t = threadIdx.x;
    int v[4], s = 0;
#pragma unroll
    for (int j = 0; j < 4; j++) {
        int i = b * STILE + t * 4 + j;
        int x = (i < NN) ? g_deg[i] : 0;
        s += x; v[j] = s;
    }
    __shared__ int ss[256];
    ss[t] = s;
    __syncthreads();
    for (int o = 1; o < 256; o <<= 1) {
        int x = (t >= o) ? ss[t - o] : 0;
        __syncthreads();
        ss[t] += x;
        __syncthreads();
    }
    int excl = ss[t] - s + g_tsum[b];
#pragma unroll
    for (int j = 0; j < 4; j++) {
        int i = b * STILE + t * 4 + j;
        if (i < NN) g_rowptr[i + 1] = excl + v[j];
    }
    if (b == 0 && t == 0) g_rowptr[0] = 0;
}
__global__ void fill_kernel(const int* __restrict__ ei) {
    int e = blockIdx.x * blockDim.x + threadIdx.x;
    if (e < NE) {
        int src = edge_at(ei, e);
        int dst = edge_at(ei, NE + e);
        int pos = g_rowptr[dst] + atomicAdd(&g_cursor[dst], 1);
        g_col[pos] = src;
    }
}

// ---------------- weight conversion: coalesced transpose + hi/lo split ----------------
__global__ void wconv_kernel(const float* __restrict__ W1, const float* __restrict__ W2) {
    __shared__ float tile[32][33];
    int b = blockIdx.x;
    int tx = threadIdx.x & 31, ty = threadIdx.x >> 5;   // 32 x 8
    if (b < NL * 32) {
        int l = b >> 5, r = b & 31;
        int kt = r >> 3, nt = r & 7;
        const float* src = W1 + (size_t)l * 32768;
#pragma unroll
        for (int j = 0; j < 4; j++)
            tile[ty * 4 + j][tx] = __ldg(&src[(kt * 32 + ty * 4 + j) * 256 + nt * 32 + tx]);
        __syncthreads();
#pragma unroll
        for (int j = 0; j < 4; j++) {
            float w = tile[tx][ty * 4 + j];
            int n = nt * 32 + ty * 4 + j, k = kt * 32 + tx;
            size_t o = (size_t)l * 32768 + n * 128 + k;
            __nv_bfloat16 h = __float2bfloat16(w);
            g_w1h[o] = h;
            g_w1l[o] = __float2bfloat16(w - __bfloat162float(h));
        }
    } else {
        int u = b - NL * 32;
        int l = u >> 5, r = u & 31;
        int kt = r >> 2, nt = r & 3;
        const float* src = W2 + (size_t)l * 32768;
#pragma unroll
        for (int j = 0; j < 4; j++)
            tile[ty * 4 + j][tx] = __ldg(&src[(kt * 32 + ty * 4 + j) * 128 + nt * 32 + tx]);
        __syncthreads();
#pragma unroll
        for (int j = 0; j < 4; j++) {
            float w = tile[tx][ty * 4 + j];
            int n = nt * 32 + ty * 4 + j, k = kt * 32 + tx;
            size_t o = (size_t)l * 32768 + n * 256 + k;
            __nv_bfloat16 h = __float2bfloat16(w);
            g_w2h[o] = h;
            g_w2l[o] = __float2bfloat16(w - __bfloat162float(h));
        }
    }
}

// ---------------- fused gather + HMMA MLP ----------------
#define ASTR 136   // elems per A row (128 + 8 pad) -> 272B, 4-bank rotation per row
#define YSTR 264
#define WSTR 136

#define SB1_OFF 0
#define SB2_OFF 1024
#define AH_OFF  2048
#define AL_OFF  (AH_OFF + 64 * ASTR * 2)
#define YH_OFF  (AL_OFF + 64 * ASTR * 2)
#define YL_OFF  (YH_OFF + 64 * YSTR * 2)
#define WH_OFF  (YL_OFF + 64 * YSTR * 2)
#define WL_OFF  (WH_OFF + 128 * WSTR * 2)
#define SMEM_BYTES (WL_OFF + 128 * WSTR * 2)

__device__ __forceinline__ uint32_t ld16x2(const char* smem, int off_bytes) {
    return *(const uint32_t*)(smem + off_bytes);
}

__device__ __forceinline__ void stage_w(const __nv_bfloat16* gh, const __nv_bfloat16* gl,
                                        char* smem, int tid, int src_stride, int kofs) {
    int n = tid >> 1, half = tid & 1;
    const uint4* sh = (const uint4*)(gh + (size_t)n * src_stride + kofs + half * 64);
    const uint4* sl = (const uint4*)(gl + (size_t)n * src_stride + kofs + half * 64);
    char* dh = smem + WH_OFF + n * (WSTR * 2) + half * 128;
    char* dl = smem + WL_OFF + n * (WSTR * 2) + half * 128;
#pragma unroll
    for (int j = 0; j < 8; j++) {
        *(uint4*)(dh + j * 16) = __ldg(&sh[j]);
        *(uint4*)(dl + j * 16) = __ldg(&sl[j]);
    }
}

__global__ __launch_bounds__(256, 1) void mlp_fused_kernel(
    const float* __restrict__ hin,
    const float* __restrict__ b1g, const float* __restrict__ b2g,
    const __nv_bfloat16* __restrict__ w1h, const __nv_bfloat16* __restrict__ w1l,
    const __nv_bfloat16* __restrict__ w2h, const __nv_bfloat16* __restrict__ w2l,
    float* __restrict__ out, int do_relu)
{
    extern __shared__ char smem[];
    int tid = threadIdx.x, lane = tid & 31, wid = tid >> 5;
    int rg = wid & 1;        // row group (32 rows)
    int cg = wid >> 1;       // col group (32 cols)
    int row0 = blockIdx.x * 64;
    float* sb1 = (float*)(smem + SB1_OFF);
    float* sb2 = (float*)(smem + SB2_OFF);

    sb1[tid] = __ldg(&b1g[tid]);
    if (tid < 128) sb2[tid] = __ldg(&b2g[tid]);

    // ---- fused GIN aggregation: A tile = h[node] + sum_{src->node} h[src] ----
    // warp handles 8 nodes; lane owns float4 (16B) of the 128-wide row
    {
        const float4* hv = (const float4*)hin;
        int nb = row0 + wid * 8;
        for (int i = 0; i < 8; i++) {
            int node = nb + i;
            float4 acc = make_float4(0.f, 0.f, 0.f, 0.f);
            if (node < NN) {
                acc = __ldg(&hv[(size_t)node * 32 + lane]);
                int beg = __ldg(&g_rowptr[node]);
                int end = __ldg(&g_rowptr[node + 1]);
                int e = beg;
                for (; e + 4 <= end; e += 4) {
                    int s0 = __ldg(&g_col[e]);
                    int s1 = __ldg(&g_col[e + 1]);
                    int s2 = __ldg(&g_col[e + 2]);
                    int s3 = __ldg(&g_col[e + 3]);
                    float4 v0 = __ldg(&hv[(size_t)s0 * 32 + lane]);
                    float4 v1 = __ldg(&hv[(size_t)s1 * 32 + lane]);
                    float4 v2 = __ldg(&hv[(size_t)s2 * 32 + lane]);
                    float4 v3 = __ldg(&hv[(size_t)s3 * 32 + lane]);
                    acc.x += v0.x; acc.y += v0.y; acc.z += v0.z; acc.w += v0.w;
                    acc.x += v1.x; acc.y += v1.y; acc.z += v1.z; acc.w += v1.w;
                    acc.x += v2.x; acc.y += v2.y; acc.z += v2.z; acc.w += v2.w;
                    acc.x += v3.x; acc.y += v3.y; acc.z += v3.z; acc.w += v3.w;
                }
                for (; e < end; e++) {
                    int s = __ldg(&g_col[e]);
                    float4 v = __ldg(&hv[(size_t)s * 32 + lane]);
                    acc.x += v.x; acc.y += v.y; acc.z += v.z; acc.w += v.w;
                }
            }
            int r = wid * 8 + i;
            uint32_t h0, l0, h1, l1;
            split2(acc.x, acc.y, h0, l0);
            split2(acc.z, acc.w, h1, l1);
            *(uint2*)(smem + AH_OFF + r * (ASTR * 2) + lane * 8) = make_uint2(h0, h1);
            *(uint2*)(smem + AL_OFF + r * (ASTR * 2) + lane * 8) = make_uint2(l0, l1);
        }
    }

    int fr = lane >> 2;          // fragment row offset 0..7
    int fk = (lane & 3) * 2;     // fragment k offset (elems)

    // ---- GEMM1: C1[64x256] = A @ W1 (two n-halves) + bias + leaky -> Y ----
    for (int nh = 0; nh < 2; nh++) {
        __syncthreads();
        stage_w(w1h + nh * 128 * 128, w1l + nh * 128 * 128, smem, tid, 128, 0);
        __syncthreads();

        float acc[2][4][4];
#pragma unroll
        for (int s = 0; s < 2; s++)
#pragma unroll
            for (int nt = 0; nt < 4; nt++)
#pragma unroll
                for (int q = 0; q < 4; q++) acc[s][nt][q] = 0.f;

#pragma unroll
        for (int ks = 0; ks < 8; ks++) {
            int k0 = ks * 16 + fk;
            uint32_t ah[2][4], al[2][4];
#pragma unroll
            for (int s = 0; s < 2; s++) {
                int r = rg * 32 + s * 16 + fr;
                int base = r * (ASTR * 2) + k0 * 2;
                ah[s][0] = ld16x2(smem + AH_OFF, base);
                ah[s][1] = ld16x2(smem + AH_OFF, base + 8 * (ASTR * 2));
                ah[s][2] = ld16x2(smem + AH_OFF, base + 16);
                ah[s][3] = ld16x2(smem + AH_OFF, base + 8 * (ASTR * 2) + 16);
                al[s][0] = ld16x2(smem + AL_OFF, base);
                al[s][1] = ld16x2(smem + AL_OFF, base + 8 * (ASTR * 2));
                al[s][2] = ld16x2(smem + AL_OFF, base + 16);
                al[s][3] = ld16x2(smem + AL_OFF, base + 8 * (ASTR * 2) + 16);
            }
#pragma unroll
            for (int nt = 0; nt < 4; nt++) {
                int n = cg * 32 + nt * 8 + fr;
                int wb = n * (WSTR * 2) + k0 * 2;
                uint32_t bh[2] = { ld16x2(smem + WH_OFF, wb), ld16x2(smem + WH_OFF, wb + 16) };
                uint32_t bl[2] = { ld16x2(smem + WL_OFF, wb), ld16x2(smem + WL_OFF, wb + 16) };
#pragma unroll
                for (int s = 0; s < 2; s++) {
                    mma16816(acc[s][nt], ah[s], bh);
                    mma16816(acc[s][nt], ah[s], bl);
                    mma16816(acc[s][nt], al[s], bh);
                }
            }
        }

        // epilogue 1: bias + leaky, split -> Y
#pragma unroll
        for (int s = 0; s < 2; s++) {
            int r = rg * 32 + s * 16 + fr;
#pragma unroll
            for (int nt = 0; nt < 4; nt++) {
                int cgl = nh * 128 + cg * 32 + nt * 8 + fk;
                float bA = sb1[cgl], bB = sb1[cgl + 1];
                uint32_t hw, lw;
                float v0 = leaky(acc[s][nt][0] + bA);
                float v1 = leaky(acc[s][nt][1] + bB);
                split2(v0, v1, hw, lw);
                *(uint32_t*)(smem + YH_OFF + r * (YSTR * 2) + cgl * 2) = hw;
                *(uint32_t*)(smem + YL_OFF + r * (YSTR * 2) + cgl * 2) = lw;
                v0 = leaky(acc[s][nt][2] + bA);
                v1 = leaky(acc[s][nt][3] + bB);
                split2(v0, v1, hw, lw);
                *(uint32_t*)(smem + YH_OFF + (r + 8) * (YSTR * 2) + cgl * 2) = hw;
                *(uint32_t*)(smem + YL_OFF + (r + 8) * (YSTR * 2) + cgl * 2) = lw;
            }
        }
    }

    // ---- GEMM2: C2[64x128] = Y @ W2 (two k-halves) ----
    float acc2[2][4][4];
#pragma unroll
    for (int s = 0; s < 2; s++)
#pragma unroll
        for (int nt = 0; nt < 4; nt++)
#pragma unroll
            for (int q = 0; q < 4; q++) acc2[s][nt][q] = 0.f;

    for (int kp = 0; kp < 2; kp++) {
        __syncthreads();
        stage_w(w2h, w2l, smem, tid, 256, kp * 128);
        __syncthreads();

#pragma unroll
        for (int ks = 0; ks < 8; ks++) {
            int k0 = ks * 16 + fk;
            int ky = kp * 128 + k0;
            uint32_t ah[2][4], al[2][4];
#pragma unroll
            for (int s = 0; s < 2; s++) {
                int r = rg * 32 + s * 16 + fr;
                int base = r * (YSTR * 2) + ky * 2;
                ah[s][0] = ld16x2(smem + YH_OFF, base);
                ah[s][1] = ld16x2(smem + YH_OFF, base + 8 * (YSTR * 2));
                ah[s][2] = ld16x2(smem + YH_OFF, base + 16);
                ah[s][3] = ld16x2(smem + YH_OFF, base + 8 * (YSTR * 2) + 16);
                al[s][0] = ld16x2(smem + AL_OFF, 0);  // placeholder overwritten below
                al[s][0] = ld16x2(smem + YL_OFF, base);
                al[s][1] = ld16x2(smem + YL_OFF, base + 8 * (YSTR * 2));
                al[s][2] = ld16x2(smem + YL_OFF, base + 16);
                al[s][3] = ld16x2(smem + YL_OFF, base + 8 * (YSTR * 2) + 16);
            }
#pragma unroll
            for (int nt = 0; nt < 4; nt++) {
                int n = cg * 32 + nt * 8 + fr;
                int wb = n * (WSTR * 2) + k0 * 2;
                uint32_t bh[2] = { ld16x2(smem + WH_OFF, wb), ld16x2(smem + WH_OFF, wb + 16) };
                uint32_t bl[2] = { ld16x2(smem + WL_OFF, wb), ld16x2(smem + WL_OFF, wb + 16) };
#pragma unroll
                for (int s = 0; s < 2; s++) {
                    mma16816(acc2[s][nt], ah[s], bh);
                    mma16816(acc2[s][nt], ah[s], bl);
                    mma16816(acc2[s][nt], al[s], bh);
                }
            }
        }
    }

    // ---- epilogue 2: bias [+ leaky] -> global fp32 ----
#pragma unroll
    for (int s = 0; s < 2; s++) {
        int r = rg * 32 + s * 16 + fr;
#pragma unroll
        for (int nt = 0; nt < 4; nt++) {
            int c = cg * 32 + nt * 8 + fk;
            float bA = sb2[c], bB = sb2[c + 1];
            int node = row0 + r;
            if (node < NN) {
                float v0 = acc2[s][nt][0] + bA;
                float v1 = acc2[s][nt][1] + bB;
                if (do_relu) { v0 = leaky(v0); v1 = leaky(v1); }
                *(float2*)(out + (size_t)node * DD + c) = make_float2(v0, v1);
            }
            if (node + 8 < NN) {
                float v0 = acc2[s][nt][2] + bA;
                float v1 = acc2[s][nt][3] + bB;
                if (do_relu) { v0 = leaky(v0); v1 = leaky(v1); }
                *(float2*)(out + (size_t)(node + 8) * DD + c) = make_float2(v0, v1);
            }
        }
    }
}

// ---------------- launch ----------------
extern "C" void kernel_launch(void* const* d_in, const int* in_sizes, int n_in,
                              void* d_out, int out_size) {
    const float* x  = (const float*)d_in[0];
    const int*   ei = (const int*)d_in[1];
    const float* W1 = (const float*)d_in[2];
    const float* b1 = (const float*)d_in[3];
    const float* W2 = (const float*)d_in[4];
    const float* b2 = (const float*)d_in[5];
    float* out = (float*)d_out;

    float *h0p, *h1p;
    cudaGetSymbolAddress((void**)&h0p, g_h0);
    cudaGetSymbolAddress((void**)&h1p, g_h1);
    __nv_bfloat16 *w1hp, *w1lp, *w2hp, *w2lp;
    cudaGetSymbolAddress((void**)&w1hp, g_w1h);
    cudaGetSymbolAddress((void**)&w1lp, g_w1l);
    cudaGetSymbolAddress((void**)&w2hp, g_w2h);
    cudaGetSymbolAddress((void**)&w2lp, g_w2l);

    cudaFuncSetAttribute(mlp_fused_kernel, cudaFuncAttributeMaxDynamicSharedMemorySize, SMEM_BYTES);

    detect_kernel<<<1, 32>>>(ei);
    zero_kernel<<<(NN + 1023) / 1024, 1024>>>();
    hist_kernel<<<(NE + 255) / 256, 256>>>(ei);
    reduce_kernel<<<NTILE, 256>>>();
    scantop_kernel<<<1, 32>>>();
    scantile_kernel<<<NTILE, 256>>>();
    fill_kernel<<<(NE + 255) / 256, 256>>>(ei);
    wconv_kernel<<<2 * NL * 32, 256>>>(W1, W2);

    const float* hin = x;
    float* bufs[2] = { h0p, h1p };
    for (int l = 0; l < NL; l++) {
        float* ho = (l == NL - 1) ? out : bufs[l & 1];
        mlp_fused_kernel<<<(NN + 63) / 64, 256, SMEM_BYTES>>>(
            hin,
            b1 + (size_t)l * 2 * DD,
            b2 + (size_t)l * DD,
            w1hp + (size_t)l * 256 * 128, w1lp + (size_t)l * 256 * 128,
            w2hp + (size_t)l * 128 * 256, w2lp + (size_t)l * 128 * 256,
            ho, (l < NL - 1) ? 1 : 0);
        hin = ho;
    }
}

// round 7
// speedup vs baseline: 1.5741x; 1.5741x over previous
#include <cuda_runtime.h>
#include <cuda_bf16.h>
#include <cstdint>

#define NN 50000
#define NE 600000
#define DD 128
#define NL 5
#define NROWS 50048   // 782 * 64

// ---------------- scratch ----------------
__device__ int   g_is64;
__device__ int   g_deg[NN];
__device__ int   g_cursor[NN];
__device__ int   g_rowptr[NN + 1];
__device__ int   g_col[NE];
__device__ float g_h0[NN * DD];
__device__ float g_h1[NN * DD];
__device__ float g_z[NN * DD];
__device__ __nv_bfloat16 g_yh[(size_t)NROWS * 256];
__device__ __nv_bfloat16 g_yl[(size_t)NROWS * 256];

// split-bf16 weights, transposed: w1 as [L][256 n][128 k], w2 as [L][128 n][256 k]
__device__ __nv_bfloat16 g_w1h[NL * 256 * 128];
__device__ __nv_bfloat16 g_w1l[NL * 256 * 128];
__device__ __nv_bfloat16 g_w2h[NL * 128 * 256];
__device__ __nv_bfloat16 g_w2l[NL * 128 * 256];

#define STILE 1024
#define NTILE ((NN + STILE - 1) / STILE)
__device__ int g_tsum[NTILE];

// ---------------- helpers ----------------
__device__ __forceinline__ float leaky(float v) { return v > 0.f ? v : 0.2f * v; }

__device__ __forceinline__ void split2(float a, float b, uint32_t& hw, uint32_t& lw) {
    __nv_bfloat16 ha = __float2bfloat16(a);
    __nv_bfloat16 hb = __float2bfloat16(b);
    float ra = a - __bfloat162float(ha);
    float rb = b - __bfloat162float(hb);
    __nv_bfloat16 la = __float2bfloat16(ra);
    __nv_bfloat16 lb = __float2bfloat16(rb);
    hw = (uint32_t)__bfloat16_as_ushort(ha) | ((uint32_t)__bfloat16_as_ushort(hb) << 16);
    lw = (uint32_t)__bfloat16_as_ushort(la) | ((uint32_t)__bfloat16_as_ushort(lb) << 16);
}

__device__ __forceinline__ void mma16816(float* d, const uint32_t* a, const uint32_t* b) {
    asm volatile(
        "mma.sync.aligned.m16n8k16.row.col.f32.bf16.bf16.f32 "
        "{%0,%1,%2,%3}, {%4,%5,%6,%7}, {%8,%9}, {%0,%1,%2,%3};"
        : "+f"(d[0]), "+f"(d[1]), "+f"(d[2]), "+f"(d[3])
        : "r"(a[0]), "r"(a[1]), "r"(a[2]), "r"(a[3]), "r"(b[0]), "r"(b[1]));
}

// ---------------- dtype detect ----------------
__global__ void detect_kernel(const int* __restrict__ p) {
    if (threadIdx.x == 0) {
        int acc = 0;
#pragma unroll
        for (int i = 0; i < 64; i++) acc |= p[2 * i + 1];
        g_is64 = (acc == 0) ? 1 : 0;
    }
}
__device__ __forceinline__ int edge_at(const int* __restrict__ p, int idx) {
    return g_is64 ? p[2 * idx] : p[idx];
}

// ---------------- CSR build ----------------
__global__ void zero_kernel() {
    int i = blockIdx.x * blockDim.x + threadIdx.x;
    if (i < NN) { g_deg[i] = 0; g_cursor[i] = 0; }
}
__global__ void hist_kernel(const int* __restrict__ ei) {
    int e = blockIdx.x * blockDim.x + threadIdx.x;
    if (e < NE) atomicAdd(&g_deg[edge_at(ei, NE + e)], 1);
}
__global__ void reduce_kernel() {
    int b = blockIdx.x, t = threadIdx.x;
    int s = 0;
#pragma unroll
    for (int j = 0; j < 4; j++) {
        int i = b * STILE + t * 4 + j;
        if (i < NN) s += g_deg[i];
    }
#pragma unroll
    for (int o = 16; o; o >>= 1) s += __shfl_down_sync(~0u, s, o);
    __shared__ int ws[8];
    if ((t & 31) == 0) ws[t >> 5] = s;
    __syncthreads();
    if (t == 0) {
        int tot = 0;
#pragma unroll
        for (int w = 0; w < 8; w++) tot += ws[w];
        g_tsum[b] = tot;
    }
}
__global__ void scantop_kernel() {
    if (threadIdx.x == 0) {
        int a = 0;
        for (int i = 0; i < NTILE; i++) { int v = g_tsum[i]; g_tsum[i] = a; a += v; }
    }
}
__global__ void scantile_kernel() {
    int b = blockIdx.x, t = threadIdx.x;
    int v[4], s = 0;
#pragma unroll
    for (int j = 0; j < 4; j++) {
        int i = b * STILE + t * 4 + j;
        int x = (i < NN) ? g_deg[i] : 0;
        s += x; v[j] = s;
    }
    __shared__ int ss[256];
    ss[t] = s;
    __syncthreads();
    for (int o = 1; o < 256; o <<= 1) {
        int x = (t >= o) ? ss[t - o] : 0;
        __syncthreads();
        ss[t] += x;
        __syncthreads();
    }
    int excl = ss[t] - s + g_tsum[b];
#pragma unroll
    for (int j = 0; j < 4; j++) {
        int i = b * STILE + t * 4 + j;
        if (i < NN) g_rowptr[i + 1] = excl + v[j];
    }
    if (b == 0 && t == 0) g_rowptr[0] = 0;
}
__global__ void fill_kernel(const int* __restrict__ ei) {
    int e = blockIdx.x * blockDim.x + threadIdx.x;
    if (e < NE) {
        int src = edge_at(ei, e);
        int dst = edge_at(ei, NE + e);
        int pos = g_rowptr[dst] + atomicAdd(&g_cursor[dst], 1);
        g_col[pos] = src;
    }
}

// ---------------- weight conversion: coalesced transpose + hi/lo split ----------------
__global__ void wconv_kernel(const float* __restrict__ W1, const float* __restrict__ W2) {
    __shared__ float tile[32][33];
    int b = blockIdx.x;
    int tx = threadIdx.x & 31, ty = threadIdx.x >> 5;   // 32 x 8
    if (b < NL * 32) {
        int l = b >> 5, r = b & 31;
        int kt = r >> 3, nt = r & 7;
        const float* src = W1 + (size_t)l * 32768;
#pragma unroll
        for (int j = 0; j < 4; j++)
            tile[ty * 4 + j][tx] = __ldg(&src[(kt * 32 + ty * 4 + j) * 256 + nt * 32 + tx]);
        __syncthreads();
#pragma unroll
        for (int j = 0; j < 4; j++) {
            float w = tile[tx][ty * 4 + j];
            int n = nt * 32 + ty * 4 + j, k = kt * 32 + tx;
            size_t o = (size_t)l * 32768 + n * 128 + k;
            __nv_bfloat16 h = __float2bfloat16(w);
            g_w1h[o] = h;
            g_w1l[o] = __float2bfloat16(w - __bfloat162float(h));
        }
    } else {
        int u = b - NL * 32;
        int l = u >> 5, r = u & 31;
        int kt = r >> 2, nt = r & 3;
        const float* src = W2 + (size_t)l * 32768;
#pragma unroll
        for (int j = 0; j < 4; j++)
            tile[ty * 4 + j][tx] = __ldg(&src[(kt * 32 + ty * 4 + j) * 128 + nt * 32 + tx]);
        __syncthreads();
#pragma unroll
        for (int j = 0; j < 4; j++) {
            float w = tile[tx][ty * 4 + j];
            int n = nt * 32 + ty * 4 + j, k = kt * 32 + tx;
            size_t o = (size_t)l * 32768 + n * 256 + k;
            __nv_bfloat16 h = __float2bfloat16(w);
            g_w2h[o] = h;
            g_w2l[o] = __float2bfloat16(w - __bfloat162float(h));
        }
    }
}

// ---------------- aggregation ----------------
__global__ __launch_bounds__(256) void aggregate_kernel(const float* __restrict__ hin) {
    int warp = (blockIdx.x * blockDim.x + threadIdx.x) >> 5;
    int lane = threadIdx.x & 31;
    if (warp >= NN) return;
    const float4* hv = (const float4*)hin;
    float4 acc = __ldg(&hv[warp * 32 + lane]);
    int beg = g_rowptr[warp];
    int end = g_rowptr[warp + 1];
    int e = beg;
    for (; e + 4 <= end; e += 4) {
        int s0 = __ldg(&g_col[e]);
        int s1 = __ldg(&g_col[e + 1]);
        int s2 = __ldg(&g_col[e + 2]);
        int s3 = __ldg(&g_col[e + 3]);
        float4 v0 = __ldg(&hv[s0 * 32 + lane]);
        float4 v1 = __ldg(&hv[s1 * 32 + lane]);
        float4 v2 = __ldg(&hv[s2 * 32 + lane]);
        float4 v3 = __ldg(&hv[s3 * 32 + lane]);
        acc.x += v0.x; acc.y += v0.y; acc.z += v0.z; acc.w += v0.w;
        acc.x += v1.x; acc.y += v1.y; acc.z += v1.z; acc.w += v1.w;
        acc.x += v2.x; acc.y += v2.y; acc.z += v2.z; acc.w += v2.w;
        acc.x += v3.x; acc.y += v3.y; acc.z += v3.z; acc.w += v3.w;
    }
    for (; e < end; e++) {
        int s = __ldg(&g_col[e]);
        float4 v = __ldg(&hv[s * 32 + lane]);
        acc.x += v.x; acc.y += v.y; acc.z += v.z; acc.w += v.w;
    }
    ((float4*)g_z)[warp * 32 + lane] = acc;
}

// ---------------- split HMMA MLP (2 kernels, 2 CTAs/SM) ----------------
#define ASTR 136   // elems per tile row (128 + 8 pad) -> 272B, 4-bank rotation
#define WSTR 136

#define SB_OFF  0
#define AH_OFF  2048
#define AL_OFF  (AH_OFF + 64 * ASTR * 2)    // 19456
#define WH_OFF  (AL_OFF + 64 * ASTR * 2)    // 36864
#define WL_OFF  (WH_OFF + 128 * WSTR * 2)   // 71680
#define SMEM_BYTES (WL_OFF + 128 * WSTR * 2) // 106496

__device__ __forceinline__ uint32_t ld16x2(const char* smem, int off_bytes) {
    return *(const uint32_t*)(smem + off_bytes);
}

__device__ __forceinline__ void stage_w(const __nv_bfloat16* gh, const __nv_bfloat16* gl,
                                        char* smem, int tid, int src_stride, int kofs) {
    int n = tid >> 1, half = tid & 1;
    const uint4* sh = (const uint4*)(gh + (size_t)n * src_stride + kofs + half * 64);
    const uint4* sl = (const uint4*)(gl + (size_t)n * src_stride + kofs + half * 64);
    char* dh = smem + WH_OFF + n * (WSTR * 2) + half * 128;
    char* dl = smem + WL_OFF + n * (WSTR * 2) + half * 128;
#pragma unroll
    for (int j = 0; j < 8; j++) {
        *(uint4*)(dh + j * 16) = __ldg(&sh[j]);
        *(uint4*)(dl + j * 16) = __ldg(&sl[j]);
    }
}

// GEMM core: acc[2][4][4] += Atile(64x128) @ Wtile(128n x 128k)^T, warp (rg,cg)
__device__ __forceinline__ void gemm_8ks(char* smem, int rg, int cg, int fr, int fk,
                                         float acc[2][4][4]) {
#pragma unroll
    for (int ks = 0; ks < 8; ks++) {
        int k0 = ks * 16 + fk;
        uint32_t ah[2][4], al[2][4];
#pragma unroll
        for (int s = 0; s < 2; s++) {
            int r = rg * 32 + s * 16 + fr;
            int base = r * (ASTR * 2) + k0 * 2;
            ah[s][0] = ld16x2(smem + AH_OFF, base);
            ah[s][1] = ld16x2(smem + AH_OFF, base + 8 * (ASTR * 2));
            ah[s][2] = ld16x2(smem + AH_OFF, base + 16);
            ah[s][3] = ld16x2(smem + AH_OFF, base + 8 * (ASTR * 2) + 16);
            al[s][0] = ld16x2(smem + AL_OFF, base);
            al[s][1] = ld16x2(smem + AL_OFF, base + 8 * (ASTR * 2));
            al[s][2] = ld16x2(smem + AL_OFF, base + 16);
            al[s][3] = ld16x2(smem + AL_OFF, base + 8 * (ASTR * 2) + 16);
        }
#pragma unroll
        for (int nt = 0; nt < 4; nt++) {
            int n = cg * 32 + nt * 8 + fr;
            int wb = n * (WSTR * 2) + k0 * 2;
            uint32_t bh[2] = { ld16x2(smem + WH_OFF, wb), ld16x2(smem + WH_OFF, wb + 16) };
            uint32_t bl[2] = { ld16x2(smem + WL_OFF, wb), ld16x2(smem + WL_OFF, wb + 16) };
#pragma unroll
            for (int s = 0; s < 2; s++) {
                mma16816(acc[s][nt], ah[s], bh);
                mma16816(acc[s][nt], ah[s], bl);
                mma16816(acc[s][nt], al[s], bh);
            }
        }
    }
}

// ---- kernel 1: Y = leaky(Z @ W1 + b1), Y written split to global ----
__global__ __launch_bounds__(256, 2) void mlp1_kernel(
    const float* __restrict__ b1g,
    const __nv_bfloat16* __restrict__ w1h, const __nv_bfloat16* __restrict__ w1l)
{
    extern __shared__ char smem[];
    int tid = threadIdx.x, lane = tid & 31, wid = tid >> 5;
    int rg = wid & 1, cg = wid >> 1;
    int row0 = blockIdx.x * 64;
    float* sb1 = (float*)(smem + SB_OFF);
    sb1[tid] = __ldg(&b1g[tid]);

    // stage A: load z, split hi/lo
    {
        int row = tid >> 2, seg = tid & 3;
        int gr = row0 + row;
        char* dh = smem + AH_OFF + row * (ASTR * 2) + seg * 64;
        char* dl = smem + AL_OFF + row * (ASTR * 2) + seg * 64;
        if (gr < NN) {
            const float4* zg = (const float4*)g_z + (size_t)gr * 32 + seg * 8;
#pragma unroll
            for (int j = 0; j < 8; j++) {
                float4 a = __ldg(&zg[j]);
                uint32_t h0, l0, h1, l1;
                split2(a.x, a.y, h0, l0);
                split2(a.z, a.w, h1, l1);
                *(uint32_t*)(dh + j * 8)     = h0;
                *(uint32_t*)(dh + j * 8 + 4) = h1;
                *(uint32_t*)(dl + j * 8)     = l0;
                *(uint32_t*)(dl + j * 8 + 4) = l1;
            }
        } else {
#pragma unroll
            for (int j = 0; j < 8; j++) {
                *(uint2*)(dh + j * 8) = make_uint2(0, 0);
                *(uint2*)(dl + j * 8) = make_uint2(0, 0);
            }
        }
    }

    int fr = lane >> 2, fk = (lane & 3) * 2;

    for (int nh = 0; nh < 2; nh++) {
        __syncthreads();
        stage_w(w1h + nh * 128 * 128, w1l + nh * 128 * 128, smem, tid, 128, 0);
        __syncthreads();

        float acc[2][4][4];
#pragma unroll
        for (int s = 0; s < 2; s++)
#pragma unroll
            for (int nt = 0; nt < 4; nt++)
#pragma unroll
                for (int q = 0; q < 4; q++) acc[s][nt][q] = 0.f;

        gemm_8ks(smem, rg, cg, fr, fk, acc);

        // epilogue: bias + leaky, split -> global Y
#pragma unroll
        for (int s = 0; s < 2; s++) {
            int r = rg * 32 + s * 16 + fr;
            size_t gr0 = (size_t)(row0 + r) * 256;
            size_t gr1 = (size_t)(row0 + r + 8) * 256;
#pragma unroll
            for (int nt = 0; nt < 4; nt++) {
                int cgl = nh * 128 + cg * 32 + nt * 8 + fk;
                float bA = sb1[cgl], bB = sb1[cgl + 1];
                uint32_t hw, lw;
                float v0 = leaky(acc[s][nt][0] + bA);
                float v1 = leaky(acc[s][nt][1] + bB);
                split2(v0, v1, hw, lw);
                *(uint32_t*)(g_yh + gr0 + cgl) = hw;
                *(uint32_t*)(g_yl + gr0 + cgl) = lw;
                v0 = leaky(acc[s][nt][2] + bA);
                v1 = leaky(acc[s][nt][3] + bB);
                split2(v0, v1, hw, lw);
                *(uint32_t*)(g_yh + gr1 + cgl) = hw;
                *(uint32_t*)(g_yl + gr1 + cgl) = lw;
            }
        }
    }
}

// ---- kernel 2: out = Y @ W2 + b2 [, leaky] ----
__global__ __launch_bounds__(256, 2) void mlp2_kernel(
    const float* __restrict__ b2g,
    const __nv_bfloat16* __restrict__ w2h, const __nv_bfloat16* __restrict__ w2l,
    float* __restrict__ out, int do_relu)
{
    extern __shared__ char smem[];
    int tid = threadIdx.x, lane = tid & 31, wid = tid >> 5;
    int rg = wid & 1, cg = wid >> 1;
    int row0 = blockIdx.x * 64;
    float* sb2 = (float*)(smem + SB_OFF);
    if (tid < 128) sb2[tid] = __ldg(&b2g[tid]);

    int fr = lane >> 2, fk = (lane & 3) * 2;

    float acc[2][4][4];
#pragma unroll
    for (int s = 0; s < 2; s++)
#pragma unroll
        for (int nt = 0; nt < 4; nt++)
#pragma unroll
            for (int q = 0; q < 4; q++) acc[s][nt][q] = 0.f;

    for (int kp = 0; kp < 2; kp++) {
        __syncthreads();
        // stage Y k-half (64 rows x 128 cols bf16 hi/lo) into A slots
        {
            int row = tid >> 2, seg = tid & 3;
            size_t src = (size_t)(row0 + row) * 256 + kp * 128 + seg * 32;
            char* dh = smem + AH_OFF + row * (ASTR * 2) + seg * 64;
            char* dl = smem + AL_OFF + row * (ASTR * 2) + seg * 64;
            const uint4* sh = (const uint4*)(g_yh + src);
            const uint4* sl = (const uint4*)(g_yl + src);
#pragma unroll
            for (int j = 0; j < 4; j++) {
                *(uint4*)(dh + j * 16) = __ldg(&sh[j]);
                *(uint4*)(dl + j * 16) = __ldg(&sl[j]);
            }
        }
        stage_w(w2h, w2l, smem, tid, 256, kp * 128);
        __syncthreads();

        gemm_8ks(smem, rg, cg, fr, fk, acc);
    }

    // epilogue: bias [+ leaky] -> out
#pragma unroll
    for (int s = 0; s < 2; s++) {
        int r = rg * 32 + s * 16 + fr;
#pragma unroll
        for (int nt = 0; nt < 4; nt++) {
            int c = cg * 32 + nt * 8 + fk;
            float bA = sb2[c], bB = sb2[c + 1];
            int node = row0 + r;
            if (node < NN) {
                float v0 = acc[s][nt][0] + bA;
                float v1 = acc[s][nt][1] + bB;
                if (do_relu) { v0 = leaky(v0); v1 = leaky(v1); }
                *(float2*)(out + (size_t)node * DD + c) = make_float2(v0, v1);
            }
            if (node + 8 < NN) {
                float v0 = acc[s][nt][2] + bA;
                float v1 = acc[s][nt][3] + bB;
                if (do_relu) { v0 = leaky(v0); v1 = leaky(v1); }
                *(float2*)(out + (size_t)(node + 8) * DD + c) = make_float2(v0, v1);
            }
        }
    }
}

// ---------------- launch ----------------
extern "C" void kernel_launch(void* const* d_in, const int* in_sizes, int n_in,
                              void* d_out, int out_size) {
    const float* x  = (const float*)d_in[0];
    const int*   ei = (const int*)d_in[1];
    const float* W1 = (const float*)d_in[2];
    const float* b1 = (const float*)d_in[3];
    const float* W2 = (const float*)d_in[4];
    const float* b2 = (const float*)d_in[5];
    float* out = (float*)d_out;

    float *h0p, *h1p;
    cudaGetSymbolAddress((void**)&h0p, g_h0);
    cudaGetSymbolAddress((void**)&h1p, g_h1);
    __nv_bfloat16 *w1hp, *w1lp, *w2hp, *w2lp;
    cudaGetSymbolAddress((void**)&w1hp, g_w1h);
    cudaGetSymbolAddress((void**)&w1lp, g_w1l);
    cudaGetSymbolAddress((void**)&w2hp, g_w2h);
    cudaGetSymbolAddress((void**)&w2lp, g_w2l);

    cudaFuncSetAttribute(mlp1_kernel, cudaFuncAttributeMaxDynamicSharedMemorySize, SMEM_BYTES);
    cudaFuncSetAttribute(mlp2_kernel, cudaFuncAttributeMaxDynamicSharedMemorySize, SMEM_BYTES);

    detect_kernel<<<1, 32>>>(ei);
    zero_kernel<<<(NN + 1023) / 1024, 1024>>>();
    hist_kernel<<<(NE + 255) / 256, 256>>>(ei);
    reduce_kernel<<<NTILE, 256>>>();
    scantop_kernel<<<1, 32>>>();
    scantile_kernel<<<NTILE, 256>>>();
    fill_kernel<<<(NE + 255) / 256, 256>>>(ei);
    wconv_kernel<<<2 * NL * 32, 256>>>(W1, W2);

    const float* hin = x;
    float* bufs[2] = { h0p, h1p };
    int nblk = (NN + 63) / 64;
    for (int l = 0; l < NL; l++) {
        aggregate_kernel<<<(NN * 32 + 255) / 256, 256>>>(hin);
        float* ho = (l == NL - 1) ? out : bufs[l & 1];
        mlp1_kernel<<<nblk, 256, SMEM_BYTES>>>(
            b1 + (size_t)l * 2 * DD,
            w1hp + (size_t)l * 256 * 128, w1lp + (size_t)l * 256 * 128);
        mlp2_kernel<<<nblk, 256, SMEM_BYTES>>>(
            b2 + (size_t)l * DD,
            w2hp + (size_t)l * 128 * 256, w2lp + (size_t)l * 128 * 256,
            ho, (l < NL - 1) ? 1 : 0);
        hin = ho;
    }
}

// round 8
// speedup vs baseline: 2.1776x; 1.3834x over previous
#include <cuda_runtime.h>
#include <cuda_bf16.h>
#include <cstdint>

#define NN 50000
#define NE 600000
#define DD 128
#define NL 5
#define NROWS 50048   // 782 * 64

// ---------------- scratch ----------------
__device__ int   g_is64;
__device__ int   g_deg[NN];
__device__ int   g_cursor[NN];
__device__ int   g_rowptr[NN + 1];
__device__ int   g_col[NE];
__device__ float g_h0[NN * DD];
__device__ float g_h1[NN * DD];
__device__ __nv_bfloat16 g_zh[(size_t)NROWS * DD];   // split z (hi)
__device__ __nv_bfloat16 g_zl[(size_t)NROWS * DD];   // split z (lo)

// split-bf16 weights, transposed: w1 as [L][256 n][128 k], w2 as [L][128 n][256 k]
__device__ __nv_bfloat16 g_w1h[NL * 256 * 128];
__device__ __nv_bfloat16 g_w1l[NL * 256 * 128];
__device__ __nv_bfloat16 g_w2h[NL * 128 * 256];
__device__ __nv_bfloat16 g_w2l[NL * 128 * 256];

#define STILE 1024
#define NTILE ((NN + STILE - 1) / STILE)
__device__ int g_tsum[NTILE];

// ---------------- helpers ----------------
__device__ __forceinline__ float leaky(float v) { return v > 0.f ? v : 0.2f * v; }

__device__ __forceinline__ void split2(float a, float b, uint32_t& hw, uint32_t& lw) {
    __nv_bfloat16 ha = __float2bfloat16(a);
    __nv_bfloat16 hb = __float2bfloat16(b);
    float ra = a - __bfloat162float(ha);
    float rb = b - __bfloat162float(hb);
    __nv_bfloat16 la = __float2bfloat16(ra);
    __nv_bfloat16 lb = __float2bfloat16(rb);
    hw = (uint32_t)__bfloat16_as_ushort(ha) | ((uint32_t)__bfloat16_as_ushort(hb) << 16);
    lw = (uint32_t)__bfloat16_as_ushort(la) | ((uint32_t)__bfloat16_as_ushort(lb) << 16);
}

__device__ __forceinline__ void mma16816(float* d, const uint32_t* a, const uint32_t* b) {
    asm volatile(
        "mma.sync.aligned.m16n8k16.row.col.f32.bf16.bf16.f32 "
        "{%0,%1,%2,%3}, {%4,%5,%6,%7}, {%8,%9}, {%0,%1,%2,%3};"
        : "+f"(d[0]), "+f"(d[1]), "+f"(d[2]), "+f"(d[3])
        : "r"(a[0]), "r"(a[1]), "r"(a[2]), "r"(a[3]), "r"(b[0]), "r"(b[1]));
}

__device__ __forceinline__ uint32_t smem_u32(const void* p) {
    uint32_t a;
    asm("{ .reg .u64 t; cvta.to.shared.u64 t, %1; cvt.u32.u64 %0, t; }" : "=r"(a) : "l"(p));
    return a;
}

__device__ __forceinline__ void cpa16(uint32_t dst, const void* src) {
    asm volatile("cp.async.cg.shared.global [%0], [%1], 16;" :: "r"(dst), "l"(src));
}

// ---------------- dtype detect ----------------
__global__ void detect_kernel(const int* __restrict__ p) {
    if (threadIdx.x == 0) {
        int acc = 0;
#pragma unroll
        for (int i = 0; i < 64; i++) acc |= p[2 * i + 1];
        g_is64 = (acc == 0) ? 1 : 0;
    }
}
__device__ __forceinline__ int edge_at(const int* __restrict__ p, int idx) {
    return g_is64 ? p[2 * idx] : p[idx];
}

// ---------------- CSR build ----------------
__global__ void zero_kernel() {
    int i = blockIdx.x * blockDim.x + threadIdx.x;
    if (i < NN) { g_deg[i] = 0; g_cursor[i] = 0; }
}
__global__ void hist_kernel(const int* __restrict__ ei) {
    int e = blockIdx.x * blockDim.x + threadIdx.x;
    if (e < NE) atomicAdd(&g_deg[edge_at(ei, NE + e)], 1);
}
__global__ void reduce_kernel() {
    int b = blockIdx.x, t = threadIdx.x;
    int s = 0;
#pragma unroll
    for (int j = 0; j < 4; j++) {
        int i = b * STILE + t * 4 + j;
        if (i < NN) s += g_deg[i];
    }
#pragma unroll
    for (int o = 16; o; o >>= 1) s += __shfl_down_sync(~0u, s, o);
    __shared__ int ws[8];
    if ((t & 31) == 0) ws[t >> 5] = s;
    __syncthreads();
    if (t == 0) {
        int tot = 0;
#pragma unroll
        for (int w = 0; w < 8; w++) tot += ws[w];
        g_tsum[b] = tot;
    }
}
__global__ void scantop_kernel() {
    if (threadIdx.x == 0) {
        int a = 0;
        for (int i = 0; i < NTILE; i++) { int v = g_tsum[i]; g_tsum[i] = a; a += v; }
    }
}
__global__ void scantile_kernel() {
    int b = blockIdx.x, t = threadIdx.x;
    int v[4], s = 0;
#pragma unroll
    for (int j = 0; j < 4; j++) {
        int i = b * STILE + t * 4 + j;
        int x = (i < NN) ? g_deg[i] : 0;
        s += x; v[j] = s;
    }
    __shared__ int ss[256];
    ss[t] = s;
    __syncthreads();
    for (int o = 1; o < 256; o <<= 1) {
        int x = (t >= o) ? ss[t - o] : 0;
        __syncthreads();
        ss[t] += x;
        __syncthreads();
    }
    int excl = ss[t] - s + g_tsum[b];
#pragma unroll
    for (int j = 0; j < 4; j++) {
        int i = b * STILE + t * 4 + j;
        if (i < NN) g_rowptr[i + 1] = excl + v[j];
    }
    if (b == 0 && t == 0) g_rowptr[0] = 0;
}
__global__ void fill_kernel(const int* __restrict__ ei) {
    int e = blockIdx.x * blockDim.x + threadIdx.x;
    if (e < NE) {
        int src = edge_at(ei, e);
        int dst = edge_at(ei, NE + e);
        int pos = g_rowptr[dst] + atomicAdd(&g_cursor[dst], 1);
        g_col[pos] = src;
    }
}

// ---------------- weight conversion: coalesced transpose + hi/lo split ----------------
__global__ void wconv_kernel(const float* __restrict__ W1, const float* __restrict__ W2) {
    __shared__ float tile[32][33];
    int b = blockIdx.x;
    int tx = threadIdx.x & 31, ty = threadIdx.x >> 5;   // 32 x 8
    if (b < NL * 32) {
        int l = b >> 5, r = b & 31;
        int kt = r >> 3, nt = r & 7;
        const float* src = W1 + (size_t)l * 32768;
#pragma unroll
        for (int j = 0; j < 4; j++)
            tile[ty * 4 + j][tx] = __ldg(&src[(kt * 32 + ty * 4 + j) * 256 + nt * 32 + tx]);
        __syncthreads();
#pragma unroll
        for (int j = 0; j < 4; j++) {
            float w = tile[tx][ty * 4 + j];
            int n = nt * 32 + ty * 4 + j, k = kt * 32 + tx;
            size_t o = (size_t)l * 32768 + n * 128 + k;
            __nv_bfloat16 h = __float2bfloat16(w);
            g_w1h[o] = h;
            g_w1l[o] = __float2bfloat16(w - __bfloat162float(h));
        }
    } else {
        int u = b - NL * 32;
        int l = u >> 5, r = u & 31;
        int kt = r >> 2, nt = r & 3;
        const float* src = W2 + (size_t)l * 32768;
#pragma unroll
        for (int j = 0; j < 4; j++)
            tile[ty * 4 + j][tx] = __ldg(&src[(kt * 32 + ty * 4 + j) * 128 + nt * 32 + tx]);
        __syncthreads();
#pragma unroll
        for (int j = 0; j < 4; j++) {
            float w = tile[tx][ty * 4 + j];
            int n = nt * 32 + ty * 4 + j, k = kt * 32 + tx;
            size_t o = (size_t)l * 32768 + n * 256 + k;
            __nv_bfloat16 h = __float2bfloat16(w);
            g_w2h[o] = h;
            g_w2l[o] = __float2bfloat16(w - __bfloat162float(h));
        }
    }
}

// ---------------- aggregation: z = h + sum(neigh h), written SPLIT bf16 ----------------
__global__ __launch_bounds__(256) void aggregate_kernel(const float* __restrict__ hin) {
    int warp = (blockIdx.x * blockDim.x + threadIdx.x) >> 5;
    int lane = threadIdx.x & 31;
    if (warp >= NN) return;
    const float4* hv = (const float4*)hin;
    float4 acc = __ldg(&hv[warp * 32 + lane]);
    int beg = g_rowptr[warp];
    int end = g_rowptr[warp + 1];
    int e = beg;
    for (; e + 4 <= end; e += 4) {
        int s0 = __ldg(&g_col[e]);
        int s1 = __ldg(&g_col[e + 1]);
        int s2 = __ldg(&g_col[e + 2]);
        int s3 = __ldg(&g_col[e + 3]);
        float4 v0 = __ldg(&hv[s0 * 32 + lane]);
        float4 v1 = __ldg(&hv[s1 * 32 + lane]);
        float4 v2 = __ldg(&hv[s2 * 32 + lane]);
        float4 v3 = __ldg(&hv[s3 * 32 + lane]);
        acc.x += v0.x; acc.y += v0.y; acc.z += v0.z; acc.w += v0.w;
        acc.x += v1.x; acc.y += v1.y; acc.z += v1.z; acc.w += v1.w;
        acc.x += v2.x; acc.y += v2.y; acc.z += v2.z; acc.w += v2.w;
        acc.x += v3.x; acc.y += v3.y; acc.z += v3.z; acc.w += v3.w;
    }
    for (; e < end; e++) {
        int s = __ldg(&g_col[e]);
        float4 v = __ldg(&hv[s * 32 + lane]);
        acc.x += v.x; acc.y += v.y; acc.z += v.z; acc.w += v.w;
    }
    uint32_t h0, l0, h1, l1;
    split2(acc.x, acc.y, h0, l0);
    split2(acc.z, acc.w, h1, l1);
    *(uint2*)(g_zh + (size_t)warp * DD + lane * 4) = make_uint2(h0, h1);
    *(uint2*)(g_zl + (size_t)warp * DD + lane * 4) = make_uint2(l0, l1);
}

// ---------------- pipelined monolithic HMMA MLP ----------------
#define ASTR 136    // A row: 272B (4-bank rotation per row)
#define YSTR 264    // Y row: 528B
#define WSTRC 72    // W chunk row: 144B (same rotation: 144 % 128 == 16)

#define SB1_OFF 0
#define SB2_OFF 1024
#define AH_OFF  2048
#define AL_OFF  (AH_OFF + 64 * ASTR * 2)     // 19456
#define YH_OFF  (AL_OFF + 64 * ASTR * 2)     // 36864
#define YL_OFF  (YH_OFF + 64 * YSTR * 2)     // 70656
#define WB_OFF  (YL_OFF + 64 * YSTR * 2)     // 104448
#define WCH     (128 * WSTRC * 2)            // 18432 bytes per h/l chunk
#define SMEM_BYTES (WB_OFF + 4 * WCH)        // 178176

__device__ __forceinline__ uint32_t ld16x2(const char* smem, int off_bytes) {
    return *(const uint32_t*)(smem + off_bytes);
}

// stage W chunk i (0..3: W1 [nh=i>>1, kc=i&1]; 4..7: W2 k-chunk i-4) into buffer i&1
__device__ __forceinline__ void stage_chunk(uint32_t sb, int i,
    const __nv_bfloat16* w1h, const __nv_bfloat16* w1l,
    const __nv_bfloat16* w2h, const __nv_bfloat16* w2l, int tid)
{
    int n = tid >> 1, half = tid & 1;
    const __nv_bfloat16 *sh, *sl;
    if (i < 4) {
        size_t o = (size_t)(((i >> 1) * 128) + n) * 128 + (i & 1) * 64 + half * 32;
        sh = w1h + o; sl = w1l + o;
    } else {
        size_t o = (size_t)n * 256 + (i - 4) * 64 + half * 32;
        sh = w2h + o; sl = w2l + o;
    }
    uint32_t dh = sb + WB_OFF + (uint32_t)(i & 1) * 2 * WCH + n * (WSTRC * 2) + half * 64;
    uint32_t dl = dh + WCH;
#pragma unroll
    for (int j = 0; j < 4; j++) {
        cpa16(dh + j * 16, sh + j * 8);
        cpa16(dl + j * 16, sl + j * 8);
    }
}

// 4-ks GEMM on one W chunk: acc += A[64 x 64k @ basek] @ Wchunk(128n x 64k)^T
template<int AOH, int AOL, int ASTRB>
__device__ __forceinline__ void gemm4(char* smem, int basek, int wboff,
                                      int rg, int cg, int fr, int fk,
                                      float acc[2][4][4])
{
#pragma unroll
    for (int ks = 0; ks < 4; ks++) {
        int kA = basek + ks * 16 + fk;
        uint32_t ah[2][4], al[2][4];
#pragma unroll
        for (int s = 0; s < 2; s++) {
            int r = rg * 32 + s * 16 + fr;
            int base = r * ASTRB + kA * 2;
            ah[s][0] = ld16x2(smem + AOH, base);
            ah[s][1] = ld16x2(smem + AOH, base + 8 * ASTRB);
            ah[s][2] = ld16x2(smem + AOH, base + 16);
            ah[s][3] = ld16x2(smem + AOH, base + 8 * ASTRB + 16);
            al[s][0] = ld16x2(smem + AOL, base);
            al[s][1] = ld16x2(smem + AOL, base + 8 * ASTRB);
            al[s][2] = ld16x2(smem + AOL, base + 16);
            al[s][3] = ld16x2(smem + AOL, base + 8 * ASTRB + 16);
        }
        int k0c = ks * 16 + fk;
#pragma unroll
        for (int nt = 0; nt < 4; nt++) {
            int n = cg * 32 + nt * 8 + fr;
            int wb = wboff + n * (WSTRC * 2) + k0c * 2;
            uint32_t bh[2] = { ld16x2(smem, wb), ld16x2(smem, wb + 16) };
            uint32_t bl[2] = { ld16x2(smem, wb + WCH), ld16x2(smem, wb + WCH + 16) };
#pragma unroll
            for (int s = 0; s < 2; s++) {
                mma16816(acc[s][nt], ah[s], bh);
                mma16816(acc[s][nt], ah[s], bl);
                mma16816(acc[s][nt], al[s], bh);
            }
        }
    }
}

__global__ __launch_bounds__(256, 1) void mlp_mma_kernel(
    const float* __restrict__ b1g, const float* __restrict__ b2g,
    const __nv_bfloat16* __restrict__ w1h, const __nv_bfloat16* __restrict__ w1l,
    const __nv_bfloat16* __restrict__ w2h, const __nv_bfloat16* __restrict__ w2l,
    float* __restrict__ out, int do_relu)
{
    extern __shared__ char smem[];
    uint32_t sb = smem_u32(smem);
    int tid = threadIdx.x, lane = tid & 31, wid = tid >> 5;
    int rg = wid & 1, cg = wid >> 1;
    int row0 = blockIdx.x * 64;
    float* sb1 = (float*)(smem + SB1_OFF);
    float* sb2 = (float*)(smem + SB2_OFF);

    sb1[tid] = __ldg(&b1g[tid]);
    if (tid < 128) sb2[tid] = __ldg(&b2g[tid]);

    // ---- stage A tile via cp.async (z already split in global) ----
    {
        int row = tid >> 2, seg = tid & 3;
        size_t o = (size_t)(row0 + row) * DD + seg * 32;
        uint32_t dh = sb + AH_OFF + row * (ASTR * 2) + seg * 64;
        uint32_t dl = sb + AL_OFF + row * (ASTR * 2) + seg * 64;
#pragma unroll
        for (int j = 0; j < 4; j++) {
            cpa16(dh + j * 16, g_zh + o + j * 8);
            cpa16(dl + j * 16, g_zl + o + j * 8);
        }
    }
    stage_chunk(sb, 0, w1h, w1l, w2h, w2l, tid);
    asm volatile("cp.async.commit_group;" ::: "memory");   // group 0 = A + chunk0

    int fr = lane >> 2, fk = (lane & 3) * 2;
    float acc[2][4][4];

    for (int c = 0; c < 8; c++) {
        __syncthreads();   // all warps done with previous chunk's gemm (buffer reuse safe)
        if (c < 7) {
            stage_chunk(sb, c + 1, w1h, w1l, w2h, w2l, tid);
            asm volatile("cp.async.commit_group;" ::: "memory");
            asm volatile("cp.async.wait_group 1;" ::: "memory");
        } else {
            asm volatile("cp.async.wait_group 0;" ::: "memory");
        }
        __syncthreads();   // chunk c visible to all warps

        if (c == 0 || c == 2 || c == 4) {
#pragma unroll
            for (int s = 0; s < 2; s++)
#pragma unroll
                for (int nt = 0; nt < 4; nt++)
#pragma unroll
                    for (int q = 0; q < 4; q++) acc[s][nt][q] = 0.f;
        }

        int wboff = WB_OFF + (c & 1) * 2 * WCH;
        if (c < 4)
            gemm4<AH_OFF, AL_OFF, ASTR * 2>(smem, (c & 1) * 64, wboff, rg, cg, fr, fk, acc);
        else
            gemm4<YH_OFF, YL_OFF, YSTR * 2>(smem, (c - 4) * 64, wboff, rg, cg, fr, fk, acc);

        if (c == 1 || c == 3) {
            // epilogue 1: bias + leaky, split -> Y smem
            int nh = c >> 1;
#pragma unroll
            for (int s = 0; s < 2; s++) {
                int r = rg * 32 + s * 16 + fr;
#pragma unroll
                for (int nt = 0; nt < 4; nt++) {
                    int cgl = nh * 128 + cg * 32 + nt * 8 + fk;
                    float bA = sb1[cgl], bB = sb1[cgl + 1];
                    uint32_t hw, lw;
                    float v0 = leaky(acc[s][nt][0] + bA);
                    float v1 = leaky(acc[s][nt][1] + bB);
                    split2(v0, v1, hw, lw);
                    *(uint32_t*)(smem + YH_OFF + r * (YSTR * 2) + cgl * 2) = hw;
                    *(uint32_t*)(smem + YL_OFF + r * (YSTR * 2) + cgl * 2) = lw;
                    v0 = leaky(acc[s][nt][2] + bA);
                    v1 = leaky(acc[s][nt][3] + bB);
                    split2(v0, v1, hw, lw);
                    *(uint32_t*)(smem + YH_OFF + (r + 8) * (YSTR * 2) + cgl * 2) = hw;
                    *(uint32_t*)(smem + YL_OFF + (r + 8) * (YSTR * 2) + cgl * 2) = lw;
                }
            }
        }
    }

    // ---- epilogue 2: bias [+ leaky] -> global fp32 ----
#pragma unroll
    for (int s = 0; s < 2; s++) {
        int r = rg * 32 + s * 16 + fr;
#pragma unroll
        for (int nt = 0; nt < 4; nt++) {
            int c = cg * 32 + nt * 8 + fk;
            float bA = sb2[c], bB = sb2[c + 1];
            int node = row0 + r;
            if (node < NN) {
                float v0 = acc[s][nt][0] + bA;
                float v1 = acc[s][nt][1] + bB;
                if (do_relu) { v0 = leaky(v0); v1 = leaky(v1); }
                *(float2*)(out + (size_t)node * DD + c) = make_float2(v0, v1);
            }
            if (node + 8 < NN) {
                float v0 = acc[s][nt][2] + bA;
                float v1 = acc[s][nt][3] + bB;
                if (do_relu) { v0 = leaky(v0); v1 = leaky(v1); }
                *(float2*)(out + (size_t)(node + 8) * DD + c) = make_float2(v0, v1);
            }
        }
    }
}

// ---------------- launch ----------------
extern "C" void kernel_launch(void* const* d_in, const int* in_sizes, int n_in,
                              void* d_out, int out_size) {
    const float* x  = (const float*)d_in[0];
    const int*   ei = (const int*)d_in[1];
    const float* W1 = (const float*)d_in[2];
    const float* b1 = (const float*)d_in[3];
    const float* W2 = (const float*)d_in[4];
    const float* b2 = (const float*)d_in[5];
    float* out = (float*)d_out;

    float *h0p, *h1p;
    cudaGetSymbolAddress((void**)&h0p, g_h0);
    cudaGetSymbolAddress((void**)&h1p, g_h1);
    __nv_bfloat16 *w1hp, *w1lp, *w2hp, *w2lp;
    cudaGetSymbolAddress((void**)&w1hp, g_w1h);
    cudaGetSymbolAddress((void**)&w1lp, g_w1l);
    cudaGetSymbolAddress((void**)&w2hp, g_w2h);
    cudaGetSymbolAddress((void**)&w2lp, g_w2l);

    cudaFuncSetAttribute(mlp_mma_kernel, cudaFuncAttributeMaxDynamicSharedMemorySize, SMEM_BYTES);

    detect_kernel<<<1, 32>>>(ei);
    zero_kernel<<<(NN + 1023) / 1024, 1024>>>();
    hist_kernel<<<(NE + 255) / 256, 256>>>(ei);
    reduce_kernel<<<NTILE, 256>>>();
    scantop_kernel<<<1, 32>>>();
    scantile_kernel<<<NTILE, 256>>>();
    fill_kernel<<<(NE + 255) / 256, 256>>>(ei);
    wconv_kernel<<<2 * NL * 32, 256>>>(W1, W2);

    const float* hin = x;
    float* bufs[2] = { h0p, h1p };
    int nblk = (NN + 63) / 64;
    for (int l = 0; l < NL; l++) {
        aggregate_kernel<<<(NN * 32 + 255) / 256, 256>>>(hin);
        float* ho = (l == NL - 1) ? out : bufs[l & 1];
        mlp_mma_kernel<<<nblk, 256, SMEM_BYTES>>>(
            b1 + (size_t)l * 2 * DD,
            b2 + (size_t)l * DD,
            w1hp + (size_t)l * 256 * 128, w1lp + (size_t)l * 256 * 128,
            w2hp + (size_t)l * 128 * 256, w2lp + (size_t)l * 128 * 256,
            ho, (l < NL - 1) ? 1 : 0);
        hin = ho;
    }
}

// round 9
// speedup vs baseline: 2.8746x; 1.3201x over previous
#include <cuda_runtime.h>
#include <cuda_fp16.h>
#include <cuda_bf16.h>
#include <cstdint>

#define NN 50000
#define NE 600000
#define DD 128
#define NL 5
#define NROWS 50048   // 782 * 64

// ---------------- scratch ----------------
__device__ int   g_is64;
__device__ int   g_deg[NN];
__device__ int   g_cursor[NN];
__device__ int   g_rowptr[NN + 1];
__device__ int   g_col[NE];
__device__ float g_h0[NN * DD];
__device__ float g_h1[NN * DD];
__device__ __half g_zh[(size_t)NROWS * DD];   // split z (hi, fp16)
__device__ __half g_zl[(size_t)NROWS * DD];   // split z (lo, fp16)

// fp16 weights, transposed: w1 as [L][256 n][128 k], w2 as [L][128 n][256 k]
__device__ __half g_w1[NL * 256 * 128];
__device__ __half g_w2[NL * 128 * 256];

#define STILE 1024
#define NTILE ((NN + STILE - 1) / STILE)
__device__ int g_tsum[NTILE];

// ---------------- helpers ----------------
__device__ __forceinline__ float leaky(float v) { return v > 0.f ? v : 0.2f * v; }

// fp16 hi/lo split of two floats, packed as half2 words
__device__ __forceinline__ void split2h(float a, float b, uint32_t& hw, uint32_t& lw) {
    __half ha = __float2half_rn(a);
    __half hb = __float2half_rn(b);
    float ra = a - __half2float(ha);
    float rb = b - __half2float(hb);
    __half la = __float2half_rn(ra);
    __half lb = __float2half_rn(rb);
    hw = (uint32_t)__half_as_ushort(ha) | ((uint32_t)__half_as_ushort(hb) << 16);
    lw = (uint32_t)__half_as_ushort(la) | ((uint32_t)__half_as_ushort(lb) << 16);
}

__device__ __forceinline__ void mma16816h(float* d, const uint32_t* a, const uint32_t* b) {
    asm volatile(
        "mma.sync.aligned.m16n8k16.row.col.f32.f16.f16.f32 "
        "{%0,%1,%2,%3}, {%4,%5,%6,%7}, {%8,%9}, {%0,%1,%2,%3};"
        : "+f"(d[0]), "+f"(d[1]), "+f"(d[2]), "+f"(d[3])
        : "r"(a[0]), "r"(a[1]), "r"(a[2]), "r"(a[3]), "r"(b[0]), "r"(b[1]));
}

__device__ __forceinline__ uint32_t smem_u32(const void* p) {
    uint32_t a;
    asm("{ .reg .u64 t; cvta.to.shared.u64 t, %1; cvt.u32.u64 %0, t; }" : "=r"(a) : "l"(p));
    return a;
}

__device__ __forceinline__ void cpa16(uint32_t dst, const void* src) {
    asm volatile("cp.async.cg.shared.global [%0], [%1], 16;" :: "r"(dst), "l"(src));
}

// ---------------- dtype detect ----------------
__global__ void detect_kernel(const int* __restrict__ p) {
    if (threadIdx.x == 0) {
        int acc = 0;
#pragma unroll
        for (int i = 0; i < 64; i++) acc |= p[2 * i + 1];
        g_is64 = (acc == 0) ? 1 : 0;
    }
}
__device__ __forceinline__ int edge_at(const int* __restrict__ p, int idx) {
    return g_is64 ? p[2 * idx] : p[idx];
}

// ---------------- CSR build ----------------
__global__ void zero_kernel() {
    int i = blockIdx.x * blockDim.x + threadIdx.x;
    if (i < NN) { g_deg[i] = 0; g_cursor[i] = 0; }
}
__global__ void hist_kernel(const int* __restrict__ ei) {
    int e = blockIdx.x * blockDim.x + threadIdx.x;
    if (e < NE) atomicAdd(&g_deg[edge_at(ei, NE + e)], 1);
}
__global__ void reduce_kernel() {
    int b = blockIdx.x, t = threadIdx.x;
    int s = 0;
#pragma unroll
    for (int j = 0; j < 4; j++) {
        int i = b * STILE + t * 4 + j;
        if (i < NN) s += g_deg[i];
    }
#pragma unroll
    for (int o = 16; o; o >>= 1) s += __shfl_down_sync(~0u, s, o);
    __shared__ int ws[8];
    if ((t & 31) == 0) ws[t >> 5] = s;
    __syncthreads();
    if (t == 0) {
        int tot = 0;
#pragma unroll
        for (int w = 0; w < 8; w++) tot += ws[w];
        g_tsum[b] = tot;
    }
}
__global__ void scantop_kernel() {
    if (threadIdx.x == 0) {
        int a = 0;
        for (int i = 0; i < NTILE; i++) { int v = g_tsum[i]; g_tsum[i] = a; a += v; }
    }
}
__global__ void scantile_kernel() {
    int b = blockIdx.x, t = threadIdx.x;
    int v[4], s = 0;
#pragma unroll
    for (int j = 0; j < 4; j++) {
        int i = b * STILE + t * 4 + j;
        int x = (i < NN) ? g_deg[i] : 0;
        s += x; v[j] = s;
    }
    __shared__ int ss[256];
    ss[t] = s;
    __syncthreads();
    for (int o = 1; o < 256; o <<= 1) {
        int x = (t >= o) ? ss[t - o] : 0;
        __syncthreads();
        ss[t] += x;
        __syncthreads();
    }
    int excl = ss[t] - s + g_tsum[b];
#pragma unroll
    for (int j = 0; j < 4; j++) {
        int i = b * STILE + t * 4 + j;
        if (i < NN) g_rowptr[i + 1] = excl + v[j];
    }
    if (b == 0 && t == 0) g_rowptr[0] = 0;
}
__global__ void fill_kernel(const int* __restrict__ ei) {
    int e = blockIdx.x * blockDim.x + threadIdx.x;
    if (e < NE) {
        int src = edge_at(ei, e);
        int dst = edge_at(ei, NE + e);
        int pos = g_rowptr[dst] + atomicAdd(&g_cursor[dst], 1);
        g_col[pos] = src;
    }
}

// ---------------- weight conversion: coalesced transpose, fp16 round ----------------
__global__ void wconv_kernel(const float* __restrict__ W1, const float* __restrict__ W2) {
    __shared__ float tile[32][33];
    int b = blockIdx.x;
    int tx = threadIdx.x & 31, ty = threadIdx.x >> 5;   // 32 x 8
    if (b < NL * 32) {
        int l = b >> 5, r = b & 31;
        int kt = r >> 3, nt = r & 7;
        const float* src = W1 + (size_t)l * 32768;
#pragma unroll
        for (int j = 0; j < 4; j++)
            tile[ty * 4 + j][tx] = __ldg(&src[(kt * 32 + ty * 4 + j) * 256 + nt * 32 + tx]);
        __syncthreads();
#pragma unroll
        for (int j = 0; j < 4; j++) {
            float w = tile[tx][ty * 4 + j];
            int n = nt * 32 + ty * 4 + j, k = kt * 32 + tx;
            g_w1[(size_t)l * 32768 + n * 128 + k] = __float2half_rn(w);
        }
    } else {
        int u = b - NL * 32;
        int l = u >> 5, r = u & 31;
        int kt = r >> 2, nt = r & 3;
        const float* src = W2 + (size_t)l * 32768;
#pragma unroll
        for (int j = 0; j < 4; j++)
            tile[ty * 4 + j][tx] = __ldg(&src[(kt * 32 + ty * 4 + j) * 128 + nt * 32 + tx]);
        __syncthreads();
#pragma unroll
        for (int j = 0; j < 4; j++) {
            float w = tile[tx][ty * 4 + j];
            int n = nt * 32 + ty * 4 + j, k = kt * 32 + tx;
            g_w2[(size_t)l * 32768 + n * 256 + k] = __float2half_rn(w);
        }
    }
}

// ---------------- aggregation: z = h + sum(neigh h), written SPLIT fp16 ----------------
__global__ __launch_bounds__(256) void aggregate_kernel(const float* __restrict__ hin) {
    int warp = (blockIdx.x * blockDim.x + threadIdx.x) >> 5;
    int lane = threadIdx.x & 31;
    if (warp >= NN) return;
    const float4* hv = (const float4*)hin;
    float4 acc = __ldg(&hv[warp * 32 + lane]);
    int beg = g_rowptr[warp];
    int end = g_rowptr[warp + 1];
    int e = beg;
    for (; e + 4 <= end; e += 4) {
        int s0 = __ldg(&g_col[e]);
        int s1 = __ldg(&g_col[e + 1]);
        int s2 = __ldg(&g_col[e + 2]);
        int s3 = __ldg(&g_col[e + 3]);
        float4 v0 = __ldg(&hv[s0 * 32 + lane]);
        float4 v1 = __ldg(&hv[s1 * 32 + lane]);
        float4 v2 = __ldg(&hv[s2 * 32 + lane]);
        float4 v3 = __ldg(&hv[s3 * 32 + lane]);
        acc.x += v0.x; acc.y += v0.y; acc.z += v0.z; acc.w += v0.w;
        acc.x += v1.x; acc.y += v1.y; acc.z += v1.z; acc.w += v1.w;
        acc.x += v2.x; acc.y += v2.y; acc.z += v2.z; acc.w += v2.w;
        acc.x += v3.x; acc.y += v3.y; acc.z += v3.z; acc.w += v3.w;
    }
    for (; e < end; e++) {
        int s = __ldg(&g_col[e]);
        float4 v = __ldg(&hv[s * 32 + lane]);
        acc.x += v.x; acc.y += v.y; acc.z += v.z; acc.w += v.w;
    }
    uint32_t h0, l0, h1, l1;
    split2h(acc.x, acc.y, h0, l0);
    split2h(acc.z, acc.w, h1, l1);
    *(uint2*)(g_zh + (size_t)warp * DD + lane * 4) = make_uint2(h0, h1);
    *(uint2*)(g_zl + (size_t)warp * DD + lane * 4) = make_uint2(l0, l1);
}

// ---------------- pipelined monolithic HMMA MLP (fp16, 2-term split) ----------------
#define ASTR 136    // A row: 272B (4-bank rotation per row)
#define YSTR 264    // Y row: 528B
#define WSTRC 72    // W chunk row: 144B (same rotation: 144 % 128 == 16)

#define SB1_OFF 0
#define SB2_OFF 1024
#define AH_OFF  2048
#define AL_OFF  (AH_OFF + 64 * ASTR * 2)     // 19456
#define YH_OFF  (AL_OFF + 64 * ASTR * 2)     // 36864
#define YL_OFF  (YH_OFF + 64 * YSTR * 2)     // 70656
#define WB_OFF  (YL_OFF + 64 * YSTR * 2)     // 104448
#define WCH     (128 * WSTRC * 2)            // 18432 bytes per chunk (hi only)
#define SMEM_BYTES (WB_OFF + 2 * WCH)        // 141312

__device__ __forceinline__ uint32_t ld16x2(const char* smem, int off_bytes) {
    return *(const uint32_t*)(smem + off_bytes);
}

// stage W chunk i (0..3: W1 [nh=i>>1, kc=i&1]; 4..7: W2 k-chunk i-4) into buffer i&1
__device__ __forceinline__ void stage_chunk(uint32_t sb, int i,
    const __half* w1, const __half* w2, int tid)
{
    int n = tid >> 1, half = tid & 1;
    const __half* sh;
    if (i < 4) {
        sh = w1 + (size_t)(((i >> 1) * 128) + n) * 128 + (i & 1) * 64 + half * 32;
    } else {
        sh = w2 + (size_t)n * 256 + (i - 4) * 64 + half * 32;
    }
    uint32_t dh = sb + WB_OFF + (uint32_t)(i & 1) * WCH + n * (WSTRC * 2) + half * 64;
#pragma unroll
    for (int j = 0; j < 4; j++)
        cpa16(dh + j * 16, sh + j * 8);
}

// 4-ks GEMM on one W chunk: acc += A[64 x 64k @ basek] @ Wchunk(128n x 64k)^T
template<int AOH, int AOL, int ASTRB>
__device__ __forceinline__ void gemm4(char* smem, int basek, int wboff,
                                      int rg, int cg, int fr, int fk,
                                      float acc[2][4][4])
{
#pragma unroll
    for (int ks = 0; ks < 4; ks++) {
        int kA = basek + ks * 16 + fk;
        uint32_t ah[2][4], al[2][4];
#pragma unroll
        for (int s = 0; s < 2; s++) {
            int r = rg * 32 + s * 16 + fr;
            int base = r * ASTRB + kA * 2;
            ah[s][0] = ld16x2(smem + AOH, base);
            ah[s][1] = ld16x2(smem + AOH, base + 8 * ASTRB);
            ah[s][2] = ld16x2(smem + AOH, base + 16);
            ah[s][3] = ld16x2(smem + AOH, base + 8 * ASTRB + 16);
            al[s][0] = ld16x2(smem + AOL, base);
            al[s][1] = ld16x2(smem + AOL, base + 8 * ASTRB);
            al[s][2] = ld16x2(smem + AOL, base + 16);
            al[s][3] = ld16x2(smem + AOL, base + 8 * ASTRB + 16);
        }
        int k0c = ks * 16 + fk;
#pragma unroll
        for (int nt = 0; nt < 4; nt++) {
            int n = cg * 32 + nt * 8 + fr;
            int wb = wboff + n * (WSTRC * 2) + k0c * 2;
            uint32_t bh[2] = { ld16x2(smem, wb), ld16x2(smem, wb + 16) };
#pragma unroll
            for (int s = 0; s < 2; s++) {
                mma16816h(acc[s][nt], ah[s], bh);
                mma16816h(acc[s][nt], al[s], bh);
            }
        }
    }
}

__global__ __launch_bounds__(256, 1) void mlp_mma_kernel(
    const float* __restrict__ b1g, const float* __restrict__ b2g,
    const __half* __restrict__ w1, const __half* __restrict__ w2,
    float* __restrict__ out, int do_relu)
{
    extern __shared__ char smem[];
    uint32_t sb = smem_u32(smem);
    int tid = threadIdx.x, lane = tid & 31, wid = tid >> 5;
    int rg = wid & 1, cg = wid >> 1;
    int row0 = blockIdx.x * 64;
    float* sb1 = (float*)(smem + SB1_OFF);
    float* sb2 = (float*)(smem + SB2_OFF);

    sb1[tid] = __ldg(&b1g[tid]);
    if (tid < 128) sb2[tid] = __ldg(&b2g[tid]);

    // ---- stage A tile via cp.async (z already split in global) ----
    {
        int row = tid >> 2, seg = tid & 3;
        size_t o = (size_t)(row0 + row) * DD + seg * 32;
        uint32_t dh = sb + AH_OFF + row * (ASTR * 2) + seg * 64;
        uint32_t dl = sb + AL_OFF + row * (ASTR * 2) + seg * 64;
#pragma unroll
        for (int j = 0; j < 4; j++) {
            cpa16(dh + j * 16, g_zh + o + j * 8);
            cpa16(dl + j * 16, g_zl + o + j * 8);
        }
    }
    stage_chunk(sb, 0, w1, w2, tid);
    asm volatile("cp.async.commit_group;" ::: "memory");   // group 0 = A + chunk0

    int fr = lane >> 2, fk = (lane & 3) * 2;
    float acc[2][4][4];

    for (int c = 0; c < 8; c++) {
        __syncthreads();   // all warps done with previous chunk's gemm (buffer reuse safe)
        if (c < 7) {
            stage_chunk(sb, c + 1, w1, w2, tid);
            asm volatile("cp.async.commit_group;" ::: "memory");
            asm volatile("cp.async.wait_group 1;" ::: "memory");
        } else {
            asm volatile("cp.async.wait_group 0;" ::: "memory");
        }
        __syncthreads();   // chunk c visible to all warps

        if (c == 0 || c == 2 || c == 4) {
#pragma unroll
            for (int s = 0; s < 2; s++)
#pragma unroll
                for (int nt = 0; nt < 4; nt++)
#pragma unroll
                    for (int q = 0; q < 4; q++) acc[s][nt][q] = 0.f;
        }

        int wboff = WB_OFF + (c & 1) * WCH;
        if (c < 4)
            gemm4<AH_OFF, AL_OFF, ASTR * 2>(smem, (c & 1) * 64, wboff, rg, cg, fr, fk, acc);
        else
            gemm4<YH_OFF, YL_OFF, YSTR * 2>(smem, (c - 4) * 64, wboff, rg, cg, fr, fk, acc);

        if (c == 1 || c == 3) {
            // epilogue 1: bias + leaky, split fp16 -> Y smem
            int nh = c >> 1;
#pragma unroll
            for (int s = 0; s < 2; s++) {
                int r = rg * 32 + s * 16 + fr;
#pragma unroll
                for (int nt = 0; nt < 4; nt++) {
                    int cgl = nh * 128 + cg * 32 + nt * 8 + fk;
                    float bA = sb1[cgl], bB = sb1[cgl + 1];
                    uint32_t hw, lw;
                    float v0 = leaky(acc[s][nt][0] + bA);
                    float v1 = leaky(acc[s][nt][1] + bB);
                    split2h(v0, v1, hw, lw);
                    *(uint32_t*)(smem + YH_OFF + r * (YSTR * 2) + cgl * 2) = hw;
                    *(uint32_t*)(smem + YL_OFF + r * (YSTR * 2) + cgl * 2) = lw;
                    v0 = leaky(acc[s][nt][2] + bA);
                    v1 = leaky(acc[s][nt][3] + bB);
                    split2h(v0, v1, hw, lw);
                    *(uint32_t*)(smem + YH_OFF + (r + 8) * (YSTR * 2) + cgl * 2) = hw;
                    *(uint32_t*)(smem + YL_OFF + (r + 8) * (YSTR * 2) + cgl * 2) = lw;
                }
            }
        }
    }

    // ---- epilogue 2: bias [+ leaky] -> global fp32 ----
#pragma unroll
    for (int s = 0; s < 2; s++) {
        int r = rg * 32 + s * 16 + fr;
#pragma unroll
        for (int nt = 0; nt < 4; nt++) {
            int c = cg * 32 + nt * 8 + fk;
            float bA = sb2[c], bB = sb2[c + 1];
            int node = row0 + r;
            if (node < NN) {
                float v0 = acc[s][nt][0] + bA;
                float v1 = acc[s][nt][1] + bB;
                if (do_relu) { v0 = leaky(v0); v1 = leaky(v1); }
                *(float2*)(out + (size_t)node * DD + c) = make_float2(v0, v1);
            }
            if (node + 8 < NN) {
                float v0 = acc[s][nt][2] + bA;
                float v1 = acc[s][nt][3] + bB;
                if (do_relu) { v0 = leaky(v0); v1 = leaky(v1); }
                *(float2*)(out + (size_t)(node + 8) * DD + c) = make_float2(v0, v1);
            }
        }
    }
}

// ---------------- launch ----------------
extern "C" void kernel_launch(void* const* d_in, const int* in_sizes, int n_in,
                              void* d_out, int out_size) {
    const float* x  = (const float*)d_in[0];
    const int*   ei = (const int*)d_in[1];
    const float* W1 = (const float*)d_in[2];
    const float* b1 = (const float*)d_in[3];
    const float* W2 = (const float*)d_in[4];
    const float* b2 = (const float*)d_in[5];
    float* out = (float*)d_out;

    float *h0p, *h1p;
    cudaGetSymbolAddress((void**)&h0p, g_h0);
    cudaGetSymbolAddress((void**)&h1p, g_h1);
    __half *w1p, *w2p;
    cudaGetSymbolAddress((void**)&w1p, g_w1);
    cudaGetSymbolAddress((void**)&w2p, g_w2);

    cudaFuncSetAttribute(mlp_mma_kernel, cudaFuncAttributeMaxDynamicSharedMemorySize, SMEM_BYTES);

    detect_kernel<<<1, 32>>>(ei);
    zero_kernel<<<(NN + 1023) / 1024, 1024>>>();
    hist_kernel<<<(NE + 255) / 256, 256>>>(ei);
    reduce_kernel<<<NTILE, 256>>>();
    scantop_kernel<<<1, 32>>>();
    scantile_kernel<<<NTILE, 256>>>();
    fill_kernel<<<(NE + 255) / 256, 256>>>(ei);
    wconv_kernel<<<2 * NL * 32, 256>>>(W1, W2);

    const float* hin = x;
    float* bufs[2] = { h0p, h1p };
    int nblk = (NN + 63) / 64;
    for (int l = 0; l < NL; l++) {
        aggregate_kernel<<<(NN * 32 + 255) / 256, 256>>>(hin);
        float* ho = (l == NL - 1) ? out : bufs[l & 1];
        mlp_mma_kernel<<<nblk, 256, SMEM_BYTES>>>(
            b1 + (size_t)l * 2 * DD,
            b2 + (size_t)l * DD,
            w1p + (size_t)l * 256 * 128,
            w2p + (size_t)l * 128 * 256,
            ho, (l < NL - 1) ? 1 : 0);
        hin = ho;
    }
}